// round 2
// baseline (speedup 1.0000x reference)
#include <cuda_runtime.h>
#include <cuda_bf16.h>

#define TWO_N 8192
#define DDIM  256
#define NHALF 4096
#define BM    128
#define BN    128
#define KC    32
#define NBJ   (TWO_N / BN)   /* 64 column blocks */
#define MARGIN 0.5f

// Deterministic scratch (no device-side allocation allowed)
__device__ float g_sqnorm[TWO_N];
__device__ float g_partial[NBJ * TWO_N];   // [col_block][row] partial exp-sums
__device__ float g_ap[NHALF];              // anchor-positive distances
__device__ float g_rowsum[TWO_N];
__device__ int   g_mask_mode;              // 0=int32, 1=uint8, 2=float32, 3=bf16
__device__ unsigned char g_mask8[(size_t)TWO_N * TWO_N];  // normalized mask (64 MB)

// ---------------------------------------------------------------------------
// Kernel 0a: detect how the bool mask was marshalled, by scanning the first
// 4KB (safe under every candidate dtype; buffer is >= 64MB in all cases).
//   bool->int32 : every word is 0 or 1
//   bool->f32   : words are 0x00000000 / 0x3F800000
//   bool->bf16  : words contain 0x3F803F80 / 0x00003F80 halfword combos
//   bool->u8    : packed 0/1 bytes -> many words > 1, none of the FP patterns
// ---------------------------------------------------------------------------
__global__ void detect_mask_kernel(const unsigned int* __restrict__ m) {
    __shared__ int has_gt1, has_f32one, has_bf16pat;
    if (threadIdx.x == 0) { has_gt1 = 0; has_f32one = 0; has_bf16pat = 0; }
    __syncthreads();
    for (int i = threadIdx.x; i < 1024; i += blockDim.x) {
        unsigned int w = m[i];
        if (w == 0x3F803F80u || w == 0x00003F80u) atomicOr(&has_bf16pat, 1);
        else if (w == 0x3F800000u)                atomicOr(&has_f32one, 1);
        else if (w > 1u)                          atomicOr(&has_gt1, 1);
    }
    __syncthreads();
    if (threadIdx.x == 0) {
        int mode;
        if (has_bf16pat)      mode = 3;
        else if (has_f32one)  mode = 2;
        else if (has_gt1)     mode = 1;
        else                  mode = 0;
        g_mask_mode = mode;
    }
}

// ---------------------------------------------------------------------------
// Kernel 0b: normalize mask into g_mask8 (one byte per element, 0/1).
// Each thread handles 4 elements.
// ---------------------------------------------------------------------------
__global__ void convert_mask_kernel(const void* __restrict__ mraw) {
    size_t t = (size_t)blockIdx.x * blockDim.x + threadIdx.x;  // element/4 index
    size_t e = t * 4;
    if (e >= (size_t)TWO_N * TWO_N) return;
    int mode = g_mask_mode;
    uchar4 o;
    if (mode == 0) {            // int32
        const int4 v = ((const int4*)mraw)[t];
        o.x = v.x != 0; o.y = v.y != 0; o.z = v.z != 0; o.w = v.w != 0;
    } else if (mode == 1) {     // uint8
        const uchar4 v = ((const uchar4*)mraw)[t];
        o.x = v.x != 0; o.y = v.y != 0; o.z = v.z != 0; o.w = v.w != 0;
    } else if (mode == 2) {     // float32
        const float4 v = ((const float4*)mraw)[t];
        o.x = v.x != 0.f; o.y = v.y != 0.f; o.z = v.z != 0.f; o.w = v.w != 0.f;
    } else {                    // bf16
        const ushort4 v = ((const ushort4*)mraw)[t];
        o.x = (v.x & 0x7FFF) != 0; o.y = (v.y & 0x7FFF) != 0;
        o.z = (v.z & 0x7FFF) != 0; o.w = (v.w & 0x7FFF) != 0;
    }
    ((uchar4*)g_mask8)[t] = o;
}

// ---------------------------------------------------------------------------
// Kernel 1: squared norms, one warp per row
// ---------------------------------------------------------------------------
__global__ void sqnorm_kernel(const float* __restrict__ E) {
    int warp = (blockIdx.x * blockDim.x + threadIdx.x) >> 5;
    int lane = threadIdx.x & 31;
    if (warp >= TWO_N) return;
    const float* row = E + (size_t)warp * DDIM;
    float s = 0.f;
#pragma unroll
    for (int j = 0; j < DDIM / 32; j++) {
        float v = row[lane + j * 32];
        s = fmaf(v, v, s);
    }
#pragma unroll
    for (int o = 16; o > 0; o >>= 1) s += __shfl_xor_sync(0xffffffffu, s, o);
    if (lane == 0) g_sqnorm[warp] = s;
}

// ---------------------------------------------------------------------------
// Kernel 2: fused tile kernel (128x128x256 Gram tile -> distances -> masked
// exp -> per-row partial sums). Diagonal-offset tiles (bj == bi + 32) also
// emit anchor-positive distances.
// ---------------------------------------------------------------------------
__global__ void __launch_bounds__(256, 2)
tile_kernel(const float* __restrict__ E) {
    __shared__ float As[KC][BM + 4];   // stride 132 words: conflict-free, 16B-aligned
    __shared__ float Bs[KC][BN + 4];

    const int bi  = blockIdx.y;
    const int bj  = blockIdx.x;
    const int tid = threadIdx.x;
    const int tm  = tid & 15;
    const int tn  = tid >> 4;

    float acc[8][8];
#pragma unroll
    for (int i = 0; i < 8; i++)
#pragma unroll
        for (int j = 0; j < 8; j++) acc[i][j] = 0.f;

    const float* Abase = E + (size_t)bi * BM * DDIM;
    const float* Bbase = E + (size_t)bj * BN * DDIM;

    for (int kb = 0; kb < DDIM; kb += KC) {
#pragma unroll
        for (int i = 0; i < 4; i++) {
            int f   = tid + i * 256;
            int row = f >> 3;
            int k4  = (f & 7) << 2;
            float4 va = *(const float4*)(Abase + row * DDIM + kb + k4);
            As[k4 + 0][row] = va.x;
            As[k4 + 1][row] = va.y;
            As[k4 + 2][row] = va.z;
            As[k4 + 3][row] = va.w;
            float4 vb = *(const float4*)(Bbase + row * DDIM + kb + k4);
            Bs[k4 + 0][row] = vb.x;
            Bs[k4 + 1][row] = vb.y;
            Bs[k4 + 2][row] = vb.z;
            Bs[k4 + 3][row] = vb.w;
        }
        __syncthreads();
#pragma unroll 8
        for (int k = 0; k < KC; k++) {
            float a[8], b[8];
            *(float4*)&a[0] = *(const float4*)&As[k][tm * 4];
            *(float4*)&a[4] = *(const float4*)&As[k][tm * 4 + 64];
            *(float4*)&b[0] = *(const float4*)&Bs[k][tn * 4];
            *(float4*)&b[4] = *(const float4*)&Bs[k][tn * 4 + 64];
#pragma unroll
            for (int i = 0; i < 8; i++)
#pragma unroll
                for (int j = 0; j < 8; j++)
                    acc[i][j] = fmaf(a[i], b[j], acc[i][j]);
        }
        __syncthreads();
    }

    // ---------------- epilogue: distances, mask, exp, per-row partials ------
    int ln[8];
    float y2[8];
#pragma unroll
    for (int j = 0; j < 8; j++) {
        ln[j] = (j < 4) ? (tn * 4 + j) : (tn * 4 + 64 + (j - 4));
        y2[j] = g_sqnorm[bj * BN + ln[j]];
    }

    const bool diag_tile = (bj == bi + 32);
    float rowpart[8];
    int   lmv[8];

#pragma unroll
    for (int i = 0; i < 8; i++) {
        int lmi = (i < 4) ? (tm * 4 + i) : (tm * 4 + 64 + (i - 4));
        lmv[i]  = lmi;
        int gmi = bi * BM + lmi;
        float x2 = g_sqnorm[gmi];

        const unsigned char* mrow = g_mask8 + (size_t)gmi * TWO_N + bj * BN;
        unsigned int mb0 = *(const unsigned int*)(mrow + tn * 4);
        unsigned int mb1 = *(const unsigned int*)(mrow + tn * 4 + 64);

        float rp = 0.f;
#pragma unroll
        for (int j = 0; j < 8; j++) {
            float sq = x2 + y2[j] - 2.f * acc[i][j];
            float dd = sqrtf(fmaxf(sq, 0.f) + 1e-12f);
            if (diag_tile && ln[j] == lmi) g_ap[gmi] = dd;  // unique writer per entry
            unsigned int mbyte = (j < 4) ? ((mb0 >> (8 * j)) & 0xffu)
                                         : ((mb1 >> (8 * (j - 4))) & 0xffu);
            if (mbyte) rp += __expf(MARGIN - dd);
        }
        rowpart[i] = rp;
    }

    // deterministic cross-thread row reduction in smem (reuse As storage)
    __syncthreads();
    float* red = &As[0][0];   // needs 128*16 = 2048 floats; As holds 32*132 = 4224
#pragma unroll
    for (int i = 0; i < 8; i++) red[lmv[i] * 16 + tn] = rowpart[i];
    __syncthreads();

    if (tid < BM) {
        float s = 0.f;
#pragma unroll
        for (int c = 0; c < 16; c++) s += red[tid * 16 + c];
        g_partial[bj * TWO_N + bi * BM + tid] = s;
    }
}

// ---------------------------------------------------------------------------
// Kernel 3: reduce partials across column blocks (fixed order -> deterministic)
// ---------------------------------------------------------------------------
__global__ void rowsum_kernel() {
    int r = blockIdx.x * blockDim.x + threadIdx.x;
    if (r >= TWO_N) return;
    float s = 0.f;
#pragma unroll
    for (int c = 0; c < NBJ; c++) s += g_partial[c * TWO_N + r];
    g_rowsum[r] = s;
}

// ---------------------------------------------------------------------------
// Kernel 4: final scalar loss
// ---------------------------------------------------------------------------
__global__ void final_kernel(float* __restrict__ out) {
    __shared__ float ssum[256];
    __shared__ int   scnt[256];
    int tid = threadIdx.x;
    float s = 0.f;
    int   c = 0;
    for (int i = tid; i < NHALF; i += 256) {
        float rs = g_rowsum[i] + g_rowsum[i + NHALF];
        float j  = logf(rs) + g_ap[i];
        if (!isnan(j)) {
            c++;
            float t = fmaxf(j, 0.f);
            s = fmaf(t, t, s);
        }
    }
    ssum[tid] = s;
    scnt[tid] = c;
    __syncthreads();
    for (int o = 128; o > 0; o >>= 1) {
        if (tid < o) { ssum[tid] += ssum[tid + o]; scnt[tid] += scnt[tid + o]; }
        __syncthreads();
    }
    if (tid == 0) {
        float cnt = fmaxf((float)scnt[0], 1.f);
        out[0] = ssum[0] / cnt * 0.5f;
    }
}

// ---------------------------------------------------------------------------
extern "C" void kernel_launch(void* const* d_in, const int* in_sizes, int n_in,
                              void* d_out, int out_size) {
    const float* E    = (const float*)d_in[0];
    const void*  mask = d_in[1];
    float*       out  = (float*)d_out;

    detect_mask_kernel<<<1, 256>>>((const unsigned int*)mask);

    {
        size_t quads = ((size_t)TWO_N * TWO_N) / 4;          // 16,777,216
        int blocks = (int)((quads + 255) / 256);             // 65,536
        convert_mask_kernel<<<blocks, 256>>>(mask);
    }

    sqnorm_kernel<<<(TWO_N * 32) / 256, 256>>>(E);

    dim3 grid(NBJ, TWO_N / BM);   // (64, 64)
    tile_kernel<<<grid, 256>>>(E);

    rowsum_kernel<<<TWO_N / 256, 256>>>();
    final_kernel<<<1, 256>>>(out);
}

// round 3
// speedup vs baseline: 1.8347x; 1.8347x over previous
#include <cuda_runtime.h>
#include <cuda_bf16.h>
#include <math.h>

#define TWO_N 8192
#define DDIM  256
#define NHALF 4096
#define BM    128
#define BN    128
#define KC    32
#define NBJ   (TWO_N / BN)   /* 64 column blocks */
#define NTILE (NBJ * (NBJ + 1) / 2)   /* 2080 lower-triangle tiles */
#define MARGIN 0.5f

// Deterministic scratch (no device-side allocation allowed)
__device__ float g_sqnorm[TWO_N];
__device__ float g_partial[NBJ * TWO_N];   // [col_block][row] partial exp-sums
__device__ float g_ap[NHALF];              // anchor-positive distances
__device__ float g_rowsum[TWO_N];
__device__ int   g_mask_mode;              // 0=int32, 1=uint8, 2=float32, 3=bf16
__device__ unsigned char g_mask8[(size_t)TWO_N * TWO_N];  // normalized mask (64 MB)

// ---------------------------------------------------------------------------
// Kernel 0a: detect how the bool mask was marshalled (scan first 4KB).
// ---------------------------------------------------------------------------
__global__ void detect_mask_kernel(const unsigned int* __restrict__ m) {
    __shared__ int has_gt1, has_f32one, has_bf16pat;
    if (threadIdx.x == 0) { has_gt1 = 0; has_f32one = 0; has_bf16pat = 0; }
    __syncthreads();
    for (int i = threadIdx.x; i < 1024; i += blockDim.x) {
        unsigned int w = m[i];
        if (w == 0x3F803F80u || w == 0x00003F80u) atomicOr(&has_bf16pat, 1);
        else if (w == 0x3F800000u)                atomicOr(&has_f32one, 1);
        else if (w > 1u)                          atomicOr(&has_gt1, 1);
    }
    __syncthreads();
    if (threadIdx.x == 0) {
        int mode;
        if (has_bf16pat)      mode = 3;
        else if (has_f32one)  mode = 2;
        else if (has_gt1)     mode = 1;
        else                  mode = 0;
        g_mask_mode = mode;
    }
}

// ---------------------------------------------------------------------------
// Kernel 0b: normalize mask into g_mask8 (one byte per element, 0/1).
// ---------------------------------------------------------------------------
__global__ void convert_mask_kernel(const void* __restrict__ mraw) {
    size_t t = (size_t)blockIdx.x * blockDim.x + threadIdx.x;  // element/4 index
    if (t * 4 >= (size_t)TWO_N * TWO_N) return;
    int mode = g_mask_mode;
    uchar4 o;
    if (mode == 0) {            // int32
        const int4 v = ((const int4*)mraw)[t];
        o.x = v.x != 0; o.y = v.y != 0; o.z = v.z != 0; o.w = v.w != 0;
    } else if (mode == 1) {     // uint8
        const uchar4 v = ((const uchar4*)mraw)[t];
        o.x = v.x != 0; o.y = v.y != 0; o.z = v.z != 0; o.w = v.w != 0;
    } else if (mode == 2) {     // float32
        const float4 v = ((const float4*)mraw)[t];
        o.x = v.x != 0.f; o.y = v.y != 0.f; o.z = v.z != 0.f; o.w = v.w != 0.f;
    } else {                    // bf16
        const ushort4 v = ((const ushort4*)mraw)[t];
        o.x = (v.x & 0x7FFF) != 0; o.y = (v.y & 0x7FFF) != 0;
        o.z = (v.z & 0x7FFF) != 0; o.w = (v.w & 0x7FFF) != 0;
    }
    ((uchar4*)g_mask8)[t] = o;
}

// ---------------------------------------------------------------------------
// Kernel 1: squared norms, one warp per row
// ---------------------------------------------------------------------------
__global__ void sqnorm_kernel(const float* __restrict__ E) {
    int warp = (blockIdx.x * blockDim.x + threadIdx.x) >> 5;
    int lane = threadIdx.x & 31;
    if (warp >= TWO_N) return;
    const float* row = E + (size_t)warp * DDIM;
    float s = 0.f;
#pragma unroll
    for (int j = 0; j < DDIM / 32; j++) {
        float v = row[lane + j * 32];
        s = fmaf(v, v, s);
    }
#pragma unroll
    for (int o = 16; o > 0; o >>= 1) s += __shfl_xor_sync(0xffffffffu, s, o);
    if (lane == 0) g_sqnorm[warp] = s;
}

// ---------------------------------------------------------------------------
// Kernel 2: symmetric fused tile kernel. Only lower-triangle tiles (bi >= bj)
// are computed; each tile contributes row partials for the bi block AND
// (via the transpose) row partials for the bj block. sqrt/exp computed once
// per symmetric pair.
// ---------------------------------------------------------------------------
__global__ void __launch_bounds__(256, 2)
tile_kernel(const float* __restrict__ E) {
    __shared__ float As[KC][BM + 4];
    __shared__ float Bs[KC][BN + 4];

    // linear tile index -> (bi, bj), bi >= bj
    int t = blockIdx.x;
    int bi = (int)((sqrt(8.0 * t + 1.0) - 1.0) * 0.5);
    while ((bi + 1) * (bi + 2) / 2 <= t) bi++;
    while (bi * (bi + 1) / 2 > t) bi--;
    int bj = t - bi * (bi + 1) / 2;

    const int tid = threadIdx.x;
    const int tm  = tid & 15;
    const int tn  = tid >> 4;

    float acc[8][8];
#pragma unroll
    for (int i = 0; i < 8; i++)
#pragma unroll
        for (int j = 0; j < 8; j++) acc[i][j] = 0.f;

    const float* Abase = E + (size_t)bi * BM * DDIM;
    const float* Bbase = E + (size_t)bj * BN * DDIM;

    for (int kb = 0; kb < DDIM; kb += KC) {
#pragma unroll
        for (int i = 0; i < 4; i++) {
            int f   = tid + i * 256;
            int row = f >> 3;
            int k4  = (f & 7) << 2;
            float4 va = *(const float4*)(Abase + row * DDIM + kb + k4);
            As[k4 + 0][row] = va.x;
            As[k4 + 1][row] = va.y;
            As[k4 + 2][row] = va.z;
            As[k4 + 3][row] = va.w;
            float4 vb = *(const float4*)(Bbase + row * DDIM + kb + k4);
            Bs[k4 + 0][row] = vb.x;
            Bs[k4 + 1][row] = vb.y;
            Bs[k4 + 2][row] = vb.z;
            Bs[k4 + 3][row] = vb.w;
        }
        __syncthreads();
#pragma unroll 8
        for (int k = 0; k < KC; k++) {
            float a[8], b[8];
            *(float4*)&a[0] = *(const float4*)&As[k][tm * 4];
            *(float4*)&a[4] = *(const float4*)&As[k][tm * 4 + 64];
            *(float4*)&b[0] = *(const float4*)&Bs[k][tn * 4];
            *(float4*)&b[4] = *(const float4*)&Bs[k][tn * 4 + 64];
#pragma unroll
            for (int i = 0; i < 8; i++)
#pragma unroll
                for (int j = 0; j < 8; j++)
                    acc[i][j] = fmaf(a[i], b[j], acc[i][j]);
        }
        __syncthreads();
    }

    // ---------------- epilogue --------------------------------------------
    const bool diag = (bi == bj);
    const bool ap_tile = (bi == bj + 32);

    int ln[8];
    float y2[8];
#pragma unroll
    for (int j = 0; j < 8; j++) {
        ln[j] = (j < 4) ? (tn * 4 + j) : (tn * 4 + 64 + (j - 4));
        y2[j] = g_sqnorm[bj * BN + ln[j]];
    }

    // transposed-direction mask: row gc = bj*BN+ln[j], cols bi*BM + (tm*4 / +64)
    unsigned int mc0[8], mc1[8];
#pragma unroll
    for (int j = 0; j < 8; j++) {
        const unsigned char* crow = g_mask8 + (size_t)(bj * BN + ln[j]) * TWO_N + bi * BM;
        mc0[j] = *(const unsigned int*)(crow + tm * 4);
        mc1[j] = *(const unsigned int*)(crow + tm * 4 + 64);
    }

    float rowpart[8], colpart[8];
#pragma unroll
    for (int j = 0; j < 8; j++) colpart[j] = 0.f;
    int lmv[8];

#pragma unroll
    for (int i = 0; i < 8; i++) {
        int lmi = (i < 4) ? (tm * 4 + i) : (tm * 4 + 64 + (i - 4));
        lmv[i]  = lmi;
        int gmi = bi * BM + lmi;
        float x2 = g_sqnorm[gmi];

        const unsigned char* mrow = g_mask8 + (size_t)gmi * TWO_N + bj * BN;
        unsigned int mb0 = *(const unsigned int*)(mrow + tn * 4);
        unsigned int mb1 = *(const unsigned int*)(mrow + tn * 4 + 64);

        float rp = 0.f;
#pragma unroll
        for (int j = 0; j < 8; j++) {
            float sq = x2 + y2[j] - 2.f * acc[i][j];
            float dd = sqrtf(fmaxf(sq, 0.f) + 1e-12f);
            if (ap_tile && ln[j] == lmv[i]) g_ap[bj * BN + lmv[i]] = dd;
            float ev = __expf(MARGIN - dd);
            unsigned int mbyte = (j < 4) ? ((mb0 >> (8 * j)) & 0xffu)
                                         : ((mb1 >> (8 * (j - 4))) & 0xffu);
            if (mbyte) rp += ev;
            unsigned int cbyte = (i < 4) ? ((mc0[j] >> (8 * i)) & 0xffu)
                                         : ((mc1[j] >> (8 * (i - 4))) & 0xffu);
            if (cbyte) colpart[j] += ev;
        }
        rowpart[i] = rp;
    }

    // reduction 1: rows of bi-block (sum over tn)
    __syncthreads();
    float* red = &As[0][0];   // 2048 floats needed; As holds 32*132 = 4224
#pragma unroll
    for (int i = 0; i < 8; i++) red[lmv[i] * 16 + tn] = rowpart[i];
    __syncthreads();
    if (tid < BM) {
        float s = 0.f;
#pragma unroll
        for (int c = 0; c < 16; c++) s += red[tid * 16 + c];
        g_partial[bj * TWO_N + bi * BM + tid] = s;
    }

    // reduction 2: rows of bj-block via transpose (sum over tm), skip if diag
    if (!diag) {
        __syncthreads();
#pragma unroll
        for (int j = 0; j < 8; j++) red[ln[j] * 16 + tm] = colpart[j];
        __syncthreads();
        if (tid < BN) {
            float s = 0.f;
#pragma unroll
            for (int c = 0; c < 16; c++) s += red[tid * 16 + c];
            g_partial[bi * TWO_N + bj * BN + tid] = s;
        }
    }
}

// ---------------------------------------------------------------------------
// Kernel 3: reduce partials across column blocks (fixed order -> deterministic)
// ---------------------------------------------------------------------------
__global__ void rowsum_kernel() {
    int r = blockIdx.x * blockDim.x + threadIdx.x;
    if (r >= TWO_N) return;
    float s = 0.f;
#pragma unroll
    for (int c = 0; c < NBJ; c++) s += g_partial[c * TWO_N + r];
    g_rowsum[r] = s;
}

// ---------------------------------------------------------------------------
// Kernel 4: final scalar loss
// ---------------------------------------------------------------------------
__global__ void final_kernel(float* __restrict__ out) {
    __shared__ float ssum[256];
    __shared__ int   scnt[256];
    int tid = threadIdx.x;
    float s = 0.f;
    int   c = 0;
    for (int i = tid; i < NHALF; i += 256) {
        float rs = g_rowsum[i] + g_rowsum[i + NHALF];
        float j  = logf(rs) + g_ap[i];
        if (!isnan(j)) {
            c++;
            float t = fmaxf(j, 0.f);
            s = fmaf(t, t, s);
        }
    }
    ssum[tid] = s;
    scnt[tid] = c;
    __syncthreads();
    for (int o = 128; o > 0; o >>= 1) {
        if (tid < o) { ssum[tid] += ssum[tid + o]; scnt[tid] += scnt[tid + o]; }
        __syncthreads();
    }
    if (tid == 0) {
        float cnt = fmaxf((float)scnt[0], 1.f);
        out[0] = ssum[0] / cnt * 0.5f;
    }
}

// ---------------------------------------------------------------------------
extern "C" void kernel_launch(void* const* d_in, const int* in_sizes, int n_in,
                              void* d_out, int out_size) {
    const float* E    = (const float*)d_in[0];
    const void*  mask = d_in[1];
    float*       out  = (float*)d_out;

    detect_mask_kernel<<<1, 256>>>((const unsigned int*)mask);

    {
        size_t quads = ((size_t)TWO_N * TWO_N) / 4;
        int blocks = (int)((quads + 255) / 256);
        convert_mask_kernel<<<blocks, 256>>>(mask);
    }

    sqnorm_kernel<<<(TWO_N * 32) / 256, 256>>>(E);

    tile_kernel<<<NTILE, 256>>>(E);   // 2080 lower-triangle tiles

    rowsum_kernel<<<TWO_N / 256, 256>>>();
    final_kernel<<<1, 256>>>(out);
}

// round 5
// speedup vs baseline: 2.7749x; 1.5125x over previous
#include <cuda_runtime.h>
#include <cuda_fp16.h>
#include <math.h>
#include <stdint.h>

#define TWO_N 8192
#define DDIM  256
#define NHALF 4096
#define BM    128
#define NBJ   64
#define NTILE (NBJ * (NBJ + 1) / 2)   /* 2080 lower-triangle pairs */
#define MARGIN 0.5f
#define NCHUNK 24                      /* 3 terms x 8 chunks of K=32 */
#define ROWB   80                      /* smem row stride bytes (32 halfs + 8 pad) */

// ------------------------- device scratch (no allocs allowed) --------------
__device__ float    g_sqnorm[TWO_N];
__device__ float    g_partial[NBJ * TWO_N];
__device__ float    g_ap[NHALF];
__device__ float    g_rowsum[TWO_N];
__device__ int      g_mask_mode;   // 0=int32 1=uint8 2=float32 3=bf16
__device__ uint32_t g_maskbits[TWO_N * (TWO_N / 32)];   // 8 MB bit mask
__device__ __half   g_ehi[TWO_N * DDIM];                // 4 MB
__device__ __half   g_elo[TWO_N * DDIM];                // 4 MB

// ------------------------- helpers -----------------------------------------
__device__ __forceinline__ uint32_t smem_u32(const void* p) {
    uint32_t a;
    asm("{ .reg .u64 t; cvta.to.shared.u64 t, %1; cvt.u32.u64 %0, t; }"
        : "=r"(a) : "l"(p));
    return a;
}
__device__ __forceinline__ void ldmx4(uint32_t* r, uint32_t addr) {
    asm volatile("ldmatrix.sync.aligned.m8n8.x4.shared.b16 {%0,%1,%2,%3}, [%4];"
                 : "=r"(r[0]), "=r"(r[1]), "=r"(r[2]), "=r"(r[3]) : "r"(addr));
}
__device__ __forceinline__ void mma16816(float* c, const uint32_t* a, const uint32_t* b) {
    asm volatile(
        "mma.sync.aligned.m16n8k16.row.col.f32.f16.f16.f32 "
        "{%0,%1,%2,%3}, {%4,%5,%6,%7}, {%8,%9}, {%0,%1,%2,%3};"
        : "+f"(c[0]), "+f"(c[1]), "+f"(c[2]), "+f"(c[3])
        : "r"(a[0]), "r"(a[1]), "r"(a[2]), "r"(a[3]), "r"(b[0]), "r"(b[1]));
}

// ------------------------- small kernels -----------------------------------
__global__ void detect_mask_kernel(const unsigned int* __restrict__ m) {
    __shared__ int has_gt1, has_f32one, has_bf16pat;
    if (threadIdx.x == 0) { has_gt1 = 0; has_f32one = 0; has_bf16pat = 0; }
    __syncthreads();
    for (int i = threadIdx.x; i < 1024; i += blockDim.x) {
        unsigned int w = m[i];
        if (w == 0x3F803F80u || w == 0x00003F80u) atomicOr(&has_bf16pat, 1);
        else if (w == 0x3F800000u)                atomicOr(&has_f32one, 1);
        else if (w > 1u)                          atomicOr(&has_gt1, 1);
    }
    __syncthreads();
    if (threadIdx.x == 0) {
        int mode;
        if (has_bf16pat)      mode = 3;
        else if (has_f32one)  mode = 2;
        else if (has_gt1)     mode = 1;
        else                  mode = 0;
        g_mask_mode = mode;
    }
}

__global__ void convert_mask_kernel(const void* __restrict__ mraw) {
    int w = blockIdx.x * blockDim.x + threadIdx.x;     // one 32-bit output word
    if (w >= TWO_N * (TWO_N / 32)) return;
    int mode = g_mask_mode;
    uint32_t bits = 0u;
    if (mode == 0) {                                   // int32
        const uint4* p = (const uint4*)mraw + (size_t)w * 8;
#pragma unroll
        for (int q = 0; q < 8; q++) {
            uint4 v = p[q];
            bits |= ((uint32_t)(v.x != 0u)) << (q * 4 + 0);
            bits |= ((uint32_t)(v.y != 0u)) << (q * 4 + 1);
            bits |= ((uint32_t)(v.z != 0u)) << (q * 4 + 2);
            bits |= ((uint32_t)(v.w != 0u)) << (q * 4 + 3);
        }
    } else if (mode == 1) {                            // uint8
        const uint4* p = (const uint4*)mraw + (size_t)w * 2;
#pragma unroll
        for (int q = 0; q < 2; q++) {
            uint4 v = p[q];
            uint32_t ws[4] = {v.x, v.y, v.z, v.w};
#pragma unroll
            for (int k = 0; k < 4; k++)
#pragma unroll
                for (int b = 0; b < 4; b++)
                    bits |= ((uint32_t)(((ws[k] >> (8 * b)) & 0xffu) != 0u))
                            << (q * 16 + k * 4 + b);
        }
    } else if (mode == 2) {                            // float32
        const uint4* p = (const uint4*)mraw + (size_t)w * 8;
#pragma unroll
        for (int q = 0; q < 8; q++) {
            uint4 v = p[q];
            bits |= ((uint32_t)((v.x & 0x7fffffffu) != 0u)) << (q * 4 + 0);
            bits |= ((uint32_t)((v.y & 0x7fffffffu) != 0u)) << (q * 4 + 1);
            bits |= ((uint32_t)((v.z & 0x7fffffffu) != 0u)) << (q * 4 + 2);
            bits |= ((uint32_t)((v.w & 0x7fffffffu) != 0u)) << (q * 4 + 3);
        }
    } else {                                           // bf16
        const uint4* p = (const uint4*)mraw + (size_t)w * 4;
#pragma unroll
        for (int q = 0; q < 4; q++) {
            uint4 v = p[q];
            uint32_t ws[4] = {v.x, v.y, v.z, v.w};
#pragma unroll
            for (int k = 0; k < 4; k++) {
                bits |= ((uint32_t)((ws[k] & 0x7fffu) != 0u))          << (q * 8 + k * 2 + 0);
                bits |= ((uint32_t)(((ws[k] >> 16) & 0x7fffu) != 0u))  << (q * 8 + k * 2 + 1);
            }
        }
    }
    g_maskbits[w] = bits;
}

__global__ void sqnorm_kernel(const float* __restrict__ E) {
    int warp = (blockIdx.x * blockDim.x + threadIdx.x) >> 5;
    int lane = threadIdx.x & 31;
    if (warp >= TWO_N) return;
    const float* row = E + (size_t)warp * DDIM;
    float s = 0.f;
#pragma unroll
    for (int j = 0; j < DDIM / 32; j++) {
        float v = row[lane + j * 32];
        s = fmaf(v, v, s);
    }
#pragma unroll
    for (int o = 16; o > 0; o >>= 1) s += __shfl_xor_sync(0xffffffffu, s, o);
    if (lane == 0) g_sqnorm[warp] = s;
}

// split E into hi/lo fp16 (2-term Markidis)
__global__ void split_kernel(const float* __restrict__ E) {
    size_t t = (size_t)blockIdx.x * blockDim.x + threadIdx.x;  // per 4 elements
    if (t * 4 >= (size_t)TWO_N * DDIM) return;
    float4 v = ((const float4*)E)[t];
    float vv[4] = {v.x, v.y, v.z, v.w};
#pragma unroll
    for (int i = 0; i < 4; i++) {
        __half h = __float2half_rn(vv[i]);
        float  r = vv[i] - __half2float(h);
        g_ehi[t * 4 + i] = h;
        g_elo[t * 4 + i] = __float2half_rn(r);
    }
}

// ------------------------- fused HMMA tile kernel ---------------------------
__global__ void __launch_bounds__(256, 2)
tile_kernel() {
    __shared__ __align__(16) unsigned char smA[2][BM * ROWB];
    __shared__ __align__(16) unsigned char smB[2][BM * ROWB];
    __shared__ float rowred[BM][2];
    __shared__ float colred[BM][4];
    __shared__ float sy2a[BM], sy2b[BM];

    // linear tile index -> (bi, bj), bi >= bj
    int t = blockIdx.x;
    int bi = (int)((sqrt(8.0 * t + 1.0) - 1.0) * 0.5);
    while ((bi + 1) * (bi + 2) / 2 <= t) bi++;
    while (bi * (bi + 1) / 2 > t) bi--;
    int bj = t - bi * (bi + 1) / 2;
    const bool diag    = (bi == bj);
    const bool ap_tile = (bi == bj + 32);

    const int tid  = threadIdx.x;
    const int wid  = tid >> 5;
    const int lane = tid & 31;
    const int wr   = wid & 3;     // warp row: 4 x 32 rows
    const int wc   = wid >> 2;    // warp col: 2 x 64 cols

    if (tid < BM) sy2a[tid] = g_sqnorm[bi * BM + tid];
    else          sy2b[tid - BM] = g_sqnorm[bj * BM + (tid - BM)];

    // global-load mapping: 512 uint4 per 128x32 tile, 2 per thread
    const int lrow0 = tid >> 2;          // rows 0..63
    const int lrow1 = lrow0 + 64;        // rows 64..127
    const int q0    = tid & 3;           // 16B quad within 64B row-chunk

    // ldmatrix per-lane byte offsets
    const uint32_t aoff = (uint32_t)((wr * 32 + (lane & 15)) * ROWB + (lane >> 4) * 16);
    const uint32_t boff = (uint32_t)((wc * 64 + ((lane >> 4) & 1) * 8 + (lane & 7)) * ROWB
                                     + ((lane >> 3) & 1) * 16);
    uint32_t aBase[2] = { smem_u32(smA[0]) + aoff, smem_u32(smA[1]) + aoff };
    uint32_t bBase[2] = { smem_u32(smB[0]) + boff, smem_u32(smB[1]) + boff };

    float acc[2][8][4];
#pragma unroll
    for (int i = 0; i < 2; i++)
#pragma unroll
        for (int j = 0; j < 8; j++)
#pragma unroll
            for (int r = 0; r < 4; r++) acc[i][j][r] = 0.f;

    // prologue: chunk 0 (term 0: hi x hi, k0 = 0)
    {
        const __half* pa = g_ehi + (size_t)bi * BM * DDIM;
        const __half* pb = g_ehi + (size_t)bj * BM * DDIM;
        uint4 a0 = *(const uint4*)(pa + (size_t)lrow0 * DDIM + q0 * 8);
        uint4 a1 = *(const uint4*)(pa + (size_t)lrow1 * DDIM + q0 * 8);
        uint4 b0 = *(const uint4*)(pb + (size_t)lrow0 * DDIM + q0 * 8);
        uint4 b1 = *(const uint4*)(pb + (size_t)lrow1 * DDIM + q0 * 8);
        *(uint4*)(&smA[0][lrow0 * ROWB + q0 * 16]) = a0;
        *(uint4*)(&smA[0][lrow1 * ROWB + q0 * 16]) = a1;
        *(uint4*)(&smB[0][lrow0 * ROWB + q0 * 16]) = b0;
        *(uint4*)(&smB[0][lrow1 * ROWB + q0 * 16]) = b1;
    }
    __syncthreads();

    for (int c = 0; c < NCHUNK; c++) {
        const int s = c & 1;
        uint4 pa0, pa1, pb0, pb1;
        const bool havenext = (c + 1 < NCHUNK);
        if (havenext) {
            int cn   = c + 1;
            int term = cn >> 3;
            int k0   = (cn & 7) * 32;
            const __half* asrc = (term == 2) ? g_elo : g_ehi;
            const __half* bsrc = (term == 1) ? g_elo : g_ehi;
            const __half* pa = asrc + (size_t)bi * BM * DDIM + k0;
            const __half* pb = bsrc + (size_t)bj * BM * DDIM + k0;
            pa0 = *(const uint4*)(pa + (size_t)lrow0 * DDIM + q0 * 8);
            pa1 = *(const uint4*)(pa + (size_t)lrow1 * DDIM + q0 * 8);
            pb0 = *(const uint4*)(pb + (size_t)lrow0 * DDIM + q0 * 8);
            pb1 = *(const uint4*)(pb + (size_t)lrow1 * DDIM + q0 * 8);
        }

        // compute: 2 k-steps of 16
#pragma unroll
        for (int ks = 0; ks < 2; ks++) {
            uint32_t afr[2][4];
            ldmx4(afr[0], aBase[s] + ks * 32);
            ldmx4(afr[1], aBase[s] + 16 * ROWB + ks * 32);
            uint32_t bfr[8][2];
#pragma unroll
            for (int fp = 0; fp < 4; fp++) {
                uint32_t r4[4];
                ldmx4(r4, bBase[s] + fp * 16 * ROWB + ks * 32);
                bfr[fp * 2 + 0][0] = r4[0]; bfr[fp * 2 + 0][1] = r4[1];
                bfr[fp * 2 + 1][0] = r4[2]; bfr[fp * 2 + 1][1] = r4[3];
            }
#pragma unroll
            for (int fm = 0; fm < 2; fm++)
#pragma unroll
                for (int fn = 0; fn < 8; fn++)
                    mma16816(acc[fm][fn], afr[fm], bfr[fn]);
        }

        if (havenext) {
            const int sn = s ^ 1;
            *(uint4*)(&smA[sn][lrow0 * ROWB + q0 * 16]) = pa0;
            *(uint4*)(&smA[sn][lrow1 * ROWB + q0 * 16]) = pa1;
            *(uint4*)(&smB[sn][lrow0 * ROWB + q0 * 16]) = pb0;
            *(uint4*)(&smB[sn][lrow1 * ROWB + q0 * 16]) = pb1;
        }
        __syncthreads();
    }

    // ------------------------------ epilogue -------------------------------
    const int lq = lane >> 2;       // 0..7
    const int lr = lane & 3;        // 0..3

    float x2v[4];                   // [fm*2+hm]
#pragma unroll
    for (int fm = 0; fm < 2; fm++)
#pragma unroll
        for (int hm = 0; hm < 2; hm++)
            x2v[fm * 2 + hm] = sy2a[wr * 32 + fm * 16 + lq + hm * 8];

    float y2v[16];                  // [fn*2+h]
#pragma unroll
    for (int fn = 0; fn < 8; fn++)
#pragma unroll
        for (int h = 0; h < 2; h++)
            y2v[fn * 2 + h] = sy2b[wc * 64 + fn * 8 + 2 * lr + h];

    uint32_t rw[8];                 // [fm*2+hm][w2]
#pragma unroll
    for (int fm = 0; fm < 2; fm++)
#pragma unroll
        for (int hm = 0; hm < 2; hm++) {
            int grow = bi * BM + wr * 32 + fm * 16 + lq + hm * 8;
#pragma unroll
            for (int k = 0; k < 2; k++)
                rw[(fm * 2 + hm) * 2 + k] =
                    g_maskbits[(size_t)grow * (TWO_N / 32) + bj * 4 + wc * 2 + k];
        }

    uint32_t cw[16];                // [fn*2+h]
#pragma unroll
    for (int fn = 0; fn < 8; fn++)
#pragma unroll
        for (int h = 0; h < 2; h++) {
            int gcol = bj * BM + wc * 64 + fn * 8 + 2 * lr + h;
            cw[fn * 2 + h] = g_maskbits[(size_t)gcol * (TWO_N / 32) + bi * 4 + wr];
        }

    float rowp[4] = {0.f, 0.f, 0.f, 0.f};
    float colp[16];
#pragma unroll
    for (int i = 0; i < 16; i++) colp[i] = 0.f;

#pragma unroll
    for (int fm = 0; fm < 2; fm++)
#pragma unroll
        for (int fn = 0; fn < 8; fn++)
#pragma unroll
            for (int r = 0; r < 4; r++) {
                int hm = r >> 1, h = r & 1;
                int mloc = wr * 32 + fm * 16 + lq + hm * 8;
                int nloc = wc * 64 + fn * 8 + 2 * lr + h;
                float sq = x2v[fm * 2 + hm] + y2v[fn * 2 + h] - 2.f * acc[fm][fn][r];
                float dd = sqrtf(fmaxf(sq, 0.f) + 1e-12f);
                if (diag && mloc == nloc) dd = 1e-6f;   // exact self-distance
                if (ap_tile && mloc == nloc) g_ap[bj * BM + mloc] = dd;
                float ev = __expf(MARGIN - dd);
                int nn = fn * 8 + 2 * lr + h;           // 0..63 within wc half
                if ((rw[(fm * 2 + hm) * 2 + (nn >> 5)] >> (nn & 31)) & 1u)
                    rowp[fm * 2 + hm] += ev;
                if ((cw[fn * 2 + h] >> (fm * 16 + lq + hm * 8)) & 1u)
                    colp[fn * 2 + h] += ev;
            }

    // row partials: reduce over the 4-lane quad (lanes sharing lq)
#pragma unroll
    for (int i = 0; i < 4; i++) {
        rowp[i] += __shfl_xor_sync(0xffffffffu, rowp[i], 1);
        rowp[i] += __shfl_xor_sync(0xffffffffu, rowp[i], 2);
    }
    if (lr == 0) {
#pragma unroll
        for (int fm = 0; fm < 2; fm++)
#pragma unroll
            for (int hm = 0; hm < 2; hm++)
                rowred[wr * 32 + fm * 16 + lq + hm * 8][wc] = rowp[fm * 2 + hm];
    }

    // col partials: reduce over lq (xor 4, 8, 16)
#pragma unroll
    for (int i = 0; i < 16; i++) {
        colp[i] += __shfl_xor_sync(0xffffffffu, colp[i], 4);
        colp[i] += __shfl_xor_sync(0xffffffffu, colp[i], 8);
        colp[i] += __shfl_xor_sync(0xffffffffu, colp[i], 16);
    }
    if (lane < 4) {
#pragma unroll
        for (int fn = 0; fn < 8; fn++)
#pragma unroll
            for (int h = 0; h < 2; h++)
                colred[wc * 64 + fn * 8 + 2 * lane + h][wr] = colp[fn * 2 + h];
    }
    __syncthreads();

    if (tid < BM) {
        g_partial[(size_t)bj * TWO_N + bi * BM + tid] = rowred[tid][0] + rowred[tid][1];
        if (!diag)
            g_partial[(size_t)bi * TWO_N + bj * BM + tid] =
                colred[tid][0] + colred[tid][1] + colred[tid][2] + colred[tid][3];
    }
}

// ------------------------- reductions --------------------------------------
__global__ void rowsum_kernel() {
    int r = blockIdx.x * blockDim.x + threadIdx.x;
    if (r >= TWO_N) return;
    float s = 0.f;
#pragma unroll
    for (int c = 0; c < NBJ; c++) s += g_partial[(size_t)c * TWO_N + r];
    g_rowsum[r] = s;
}

__global__ void final_kernel(float* __restrict__ out) {
    __shared__ float ssum[256];
    __shared__ int   scnt[256];
    int tid = threadIdx.x;
    float s = 0.f;
    int   c = 0;
    for (int i = tid; i < NHALF; i += 256) {
        float rs = g_rowsum[i] + g_rowsum[i + NHALF];
        float j  = logf(rs) + g_ap[i];
        if (!isnan(j)) {
            c++;
            float tt = fmaxf(j, 0.f);
            s = fmaf(tt, tt, s);
        }
    }
    ssum[tid] = s;
    scnt[tid] = c;
    __syncthreads();
    for (int o = 128; o > 0; o >>= 1) {
        if (tid < o) { ssum[tid] += ssum[tid + o]; scnt[tid] += scnt[tid + o]; }
        __syncthreads();
    }
    if (tid == 0) {
        float cnt = fmaxf((float)scnt[0], 1.f);
        out[0] = ssum[0] / cnt * 0.5f;
    }
}

// ---------------------------------------------------------------------------
extern "C" void kernel_launch(void* const* d_in, const int* in_sizes, int n_in,
                              void* d_out, int out_size) {
    const float* E    = (const float*)d_in[0];
    const void*  mask = d_in[1];
    float*       out  = (float*)d_out;

    detect_mask_kernel<<<1, 256>>>((const unsigned int*)mask);
    convert_mask_kernel<<<(TWO_N * (TWO_N / 32)) / 256, 256>>>(mask);
    sqnorm_kernel<<<(TWO_N * 32) / 256, 256>>>(E);
    split_kernel<<<(TWO_N * DDIM / 4) / 256, 256>>>(E);

    tile_kernel<<<NTILE, 256>>>();

    rowsum_kernel<<<TWO_N / 256, 256>>>();
    final_kernel<<<1, 256>>>(out);
}

// round 6
// speedup vs baseline: 4.6080x; 1.6606x over previous
#include <cuda_runtime.h>
#include <cuda_fp16.h>
#include <math.h>
#include <stdint.h>

#define TWO_N 8192
#define DDIM  256
#define NHALF 4096
#define BM    128
#define NBJ   64
#define NTILE (NBJ * (NBJ + 1) / 2)   /* 2080 lower-triangle pairs */
#define MARGIN 0.5f
#define NCHUNK 8                       /* 8 chunks of K=32, single fp16 term */
#define ROWB   80                      /* smem row stride bytes (32 halfs + 8 pad) */

// ------------------------- device scratch (no allocs allowed) --------------
__device__ float    g_sqnorm[TWO_N];
__device__ float    g_partial[NBJ * TWO_N];
__device__ float    g_ap[NHALF];
__device__ float    g_rowsum[TWO_N];
__device__ int      g_mask_mode;   // 0=int32 1=uint8 2=float32 3=bf16
__device__ uint32_t g_maskbits[TWO_N * (TWO_N / 32)];   // 8 MB bit mask
__device__ __half   g_eh[TWO_N * DDIM];                 // 4 MB fp16 embeddings

// ------------------------- helpers -----------------------------------------
__device__ __forceinline__ uint32_t smem_u32(const void* p) {
    uint32_t a;
    asm("{ .reg .u64 t; cvta.to.shared.u64 t, %1; cvt.u32.u64 %0, t; }"
        : "=r"(a) : "l"(p));
    return a;
}
__device__ __forceinline__ void ldmx4(uint32_t* r, uint32_t addr) {
    asm volatile("ldmatrix.sync.aligned.m8n8.x4.shared.b16 {%0,%1,%2,%3}, [%4];"
                 : "=r"(r[0]), "=r"(r[1]), "=r"(r[2]), "=r"(r[3]) : "r"(addr));
}
__device__ __forceinline__ void mma16816(float* c, const uint32_t* a, const uint32_t* b) {
    asm volatile(
        "mma.sync.aligned.m16n8k16.row.col.f32.f16.f16.f32 "
        "{%0,%1,%2,%3}, {%4,%5,%6,%7}, {%8,%9}, {%0,%1,%2,%3};"
        : "+f"(c[0]), "+f"(c[1]), "+f"(c[2]), "+f"(c[3])
        : "r"(a[0]), "r"(a[1]), "r"(a[2]), "r"(a[3]), "r"(b[0]), "r"(b[1]));
}

// ------------------------- small kernels -----------------------------------
__global__ void detect_mask_kernel(const unsigned int* __restrict__ m) {
    __shared__ int has_gt1, has_f32one, has_bf16pat;
    if (threadIdx.x == 0) { has_gt1 = 0; has_f32one = 0; has_bf16pat = 0; }
    __syncthreads();
    for (int i = threadIdx.x; i < 1024; i += blockDim.x) {
        unsigned int w = m[i];
        if (w == 0x3F803F80u || w == 0x00003F80u) atomicOr(&has_bf16pat, 1);
        else if (w == 0x3F800000u)                atomicOr(&has_f32one, 1);
        else if (w > 1u)                          atomicOr(&has_gt1, 1);
    }
    __syncthreads();
    if (threadIdx.x == 0) {
        int mode;
        if (has_bf16pat)      mode = 3;
        else if (has_f32one)  mode = 2;
        else if (has_gt1)     mode = 1;
        else                  mode = 0;
        g_mask_mode = mode;
    }
}

// fused: squared norm + fp16 conversion, one warp per row
__global__ void prep_kernel(const float* __restrict__ E) {
    int warp = (blockIdx.x * blockDim.x + threadIdx.x) >> 5;
    int lane = threadIdx.x & 31;
    if (warp >= TWO_N) return;
    const float* row = E + (size_t)warp * DDIM;
    float4 v0 = ((const float4*)row)[lane * 2];
    float4 v1 = ((const float4*)row)[lane * 2 + 1];
    float s = v0.x * v0.x;
    s = fmaf(v0.y, v0.y, s); s = fmaf(v0.z, v0.z, s); s = fmaf(v0.w, v0.w, s);
    s = fmaf(v1.x, v1.x, s); s = fmaf(v1.y, v1.y, s);
    s = fmaf(v1.z, v1.z, s); s = fmaf(v1.w, v1.w, s);
    __half2 h[4];
    h[0] = __floats2half2_rn(v0.x, v0.y);
    h[1] = __floats2half2_rn(v0.z, v0.w);
    h[2] = __floats2half2_rn(v1.x, v1.y);
    h[3] = __floats2half2_rn(v1.z, v1.w);
    *(uint4*)(g_eh + (size_t)warp * DDIM + lane * 8) = *(uint4*)h;
#pragma unroll
    for (int o = 16; o > 0; o >>= 1) s += __shfl_xor_sync(0xffffffffu, s, o);
    if (lane == 0) g_sqnorm[warp] = s;
}

// ------------------------- per-tile mask packing ----------------------------
__device__ __forceinline__ void pack_rect(const void* __restrict__ mraw, int mode,
                                          int rowbase, int colbase, int tid) {
#pragma unroll
    for (int w = tid; w < 512; w += 256) {
        int rr = w >> 2, wq = w & 3;
        size_t ebase = (size_t)(rowbase + rr) * TWO_N + colbase + wq * 32;
        uint32_t bits = 0u;
        if (mode == 0 || mode == 2) {              // int32 / float32 (4 B/elem)
            const uint4* p = (const uint4*)mraw + (ebase >> 2);
            uint32_t vm = (mode == 2) ? 0x7fffffffu : 0xffffffffu;
#pragma unroll
            for (int q = 0; q < 8; q++) {
                uint4 v = p[q];
                bits |= ((uint32_t)((v.x & vm) != 0u)) << (q * 4 + 0);
                bits |= ((uint32_t)((v.y & vm) != 0u)) << (q * 4 + 1);
                bits |= ((uint32_t)((v.z & vm) != 0u)) << (q * 4 + 2);
                bits |= ((uint32_t)((v.w & vm) != 0u)) << (q * 4 + 3);
            }
        } else if (mode == 1) {                    // uint8
            const uint4* p = (const uint4*)mraw + (ebase >> 4);
#pragma unroll
            for (int q = 0; q < 2; q++) {
                uint4 v = p[q];
                uint32_t ws[4] = {v.x, v.y, v.z, v.w};
#pragma unroll
                for (int k = 0; k < 4; k++)
#pragma unroll
                    for (int b = 0; b < 4; b++)
                        bits |= ((uint32_t)(((ws[k] >> (8 * b)) & 0xffu) != 0u))
                                << (q * 16 + k * 4 + b);
            }
        } else {                                   // bf16
            const uint4* p = (const uint4*)mraw + (ebase >> 3);
#pragma unroll
            for (int q = 0; q < 4; q++) {
                uint4 v = p[q];
                uint32_t ws[4] = {v.x, v.y, v.z, v.w};
#pragma unroll
                for (int k = 0; k < 4; k++) {
                    bits |= ((uint32_t)((ws[k] & 0x7fffu) != 0u))         << (q * 8 + k * 2 + 0);
                    bits |= ((uint32_t)(((ws[k] >> 16) & 0x7fffu) != 0u)) << (q * 8 + k * 2 + 1);
                }
            }
        }
        g_maskbits[(size_t)(rowbase + rr) * (TWO_N / 32) + (colbase >> 5) + wq] = bits;
    }
}

// ------------------------- fused HMMA tile kernel ---------------------------
__global__ void __launch_bounds__(256, 2)
tile_kernel(const void* __restrict__ mraw) {
    __shared__ __align__(16) unsigned char smA[2][BM * ROWB];
    __shared__ __align__(16) unsigned char smB[2][BM * ROWB];
    __shared__ float rowred[BM][2];
    __shared__ float colred[BM][4];
    __shared__ float sy2a[BM], sy2b[BM];

    // linear tile index -> (bi, bj), bi >= bj
    int t = blockIdx.x;
    int bi = (int)((sqrt(8.0 * t + 1.0) - 1.0) * 0.5);
    while ((bi + 1) * (bi + 2) / 2 <= t) bi++;
    while (bi * (bi + 1) / 2 > t) bi--;
    int bj = t - bi * (bi + 1) / 2;
    const bool diag    = (bi == bj);
    const bool ap_tile = (bi == bj + 32);

    const int tid  = threadIdx.x;
    const int wid  = tid >> 5;
    const int lane = tid & 31;
    const int wr   = wid & 3;     // warp row: 4 x 32 rows
    const int wc   = wid >> 2;    // warp col: 2 x 64 cols

    if (tid < BM) sy2a[tid] = g_sqnorm[bi * BM + tid];
    else          sy2b[tid - BM] = g_sqnorm[bj * BM + (tid - BM)];

    // global-load mapping: 512 uint4 per 128x32 tile, 2 per thread
    const int lrow0 = tid >> 2;          // rows 0..63
    const int lrow1 = lrow0 + 64;        // rows 64..127
    const int q0    = tid & 3;           // 16B quad within 64B row-chunk

    // prologue chunk-0 global loads (issue first, latency covered by pack)
    const __half* pa_base = g_eh + (size_t)bi * BM * DDIM;
    const __half* pb_base = g_eh + (size_t)bj * BM * DDIM;
    uint4 a0 = *(const uint4*)(pa_base + (size_t)lrow0 * DDIM + q0 * 8);
    uint4 a1 = *(const uint4*)(pa_base + (size_t)lrow1 * DDIM + q0 * 8);
    uint4 b0 = *(const uint4*)(pb_base + (size_t)lrow0 * DDIM + q0 * 8);
    uint4 b1 = *(const uint4*)(pb_base + (size_t)lrow1 * DDIM + q0 * 8);

    // per-tile mask packing (overlaps chunk-0 latency / later MMA via 2 CTA/SM)
    {
        int mode = g_mask_mode;
        pack_rect(mraw, mode, bi * BM, bj * BM, tid);
        if (!diag) pack_rect(mraw, mode, bj * BM, bi * BM, tid);
    }

    *(uint4*)(&smA[0][lrow0 * ROWB + q0 * 16]) = a0;
    *(uint4*)(&smA[0][lrow1 * ROWB + q0 * 16]) = a1;
    *(uint4*)(&smB[0][lrow0 * ROWB + q0 * 16]) = b0;
    *(uint4*)(&smB[0][lrow1 * ROWB + q0 * 16]) = b1;
    __syncthreads();

    // ldmatrix per-lane byte offsets
    const uint32_t aoff = (uint32_t)((wr * 32 + (lane & 15)) * ROWB + (lane >> 4) * 16);
    const uint32_t boff = (uint32_t)((wc * 64 + ((lane >> 4) & 1) * 8 + (lane & 7)) * ROWB
                                     + ((lane >> 3) & 1) * 16);
    uint32_t aBase[2] = { smem_u32(smA[0]) + aoff, smem_u32(smA[1]) + aoff };
    uint32_t bBase[2] = { smem_u32(smB[0]) + boff, smem_u32(smB[1]) + boff };

    float acc[2][8][4];
#pragma unroll
    for (int i = 0; i < 2; i++)
#pragma unroll
        for (int j = 0; j < 8; j++)
#pragma unroll
            for (int r = 0; r < 4; r++) acc[i][j][r] = 0.f;

    for (int c = 0; c < NCHUNK; c++) {
        const int s = c & 1;
        uint4 pa0, pa1, pb0, pb1;
        const bool havenext = (c + 1 < NCHUNK);
        if (havenext) {
            int k0 = (c + 1) * 32;
            const __half* pa = pa_base + k0;
            const __half* pb = pb_base + k0;
            pa0 = *(const uint4*)(pa + (size_t)lrow0 * DDIM + q0 * 8);
            pa1 = *(const uint4*)(pa + (size_t)lrow1 * DDIM + q0 * 8);
            pb0 = *(const uint4*)(pb + (size_t)lrow0 * DDIM + q0 * 8);
            pb1 = *(const uint4*)(pb + (size_t)lrow1 * DDIM + q0 * 8);
        }

        // compute: 2 k-steps of 16
#pragma unroll
        for (int ks = 0; ks < 2; ks++) {
            uint32_t afr[2][4];
            ldmx4(afr[0], aBase[s] + ks * 32);
            ldmx4(afr[1], aBase[s] + 16 * ROWB + ks * 32);
            uint32_t bfr[8][2];
#pragma unroll
            for (int fp = 0; fp < 4; fp++) {
                uint32_t r4[4];
                ldmx4(r4, bBase[s] + fp * 16 * ROWB + ks * 32);
                bfr[fp * 2 + 0][0] = r4[0]; bfr[fp * 2 + 0][1] = r4[1];
                bfr[fp * 2 + 1][0] = r4[2]; bfr[fp * 2 + 1][1] = r4[3];
            }
#pragma unroll
            for (int fm = 0; fm < 2; fm++)
#pragma unroll
                for (int fn = 0; fn < 8; fn++)
                    mma16816(acc[fm][fn], afr[fm], bfr[fn]);
        }

        if (havenext) {
            const int sn = s ^ 1;
            *(uint4*)(&smA[sn][lrow0 * ROWB + q0 * 16]) = pa0;
            *(uint4*)(&smA[sn][lrow1 * ROWB + q0 * 16]) = pa1;
            *(uint4*)(&smB[sn][lrow0 * ROWB + q0 * 16]) = pb0;
            *(uint4*)(&smB[sn][lrow1 * ROWB + q0 * 16]) = pb1;
        }
        __syncthreads();
    }

    // ------------------------------ epilogue -------------------------------
    const int lq = lane >> 2;       // 0..7
    const int lr = lane & 3;        // 0..3

    float x2v[4];                   // [fm*2+hm]
#pragma unroll
    for (int fm = 0; fm < 2; fm++)
#pragma unroll
        for (int hm = 0; hm < 2; hm++)
            x2v[fm * 2 + hm] = sy2a[wr * 32 + fm * 16 + lq + hm * 8];

    float y2v[16];                  // [fn*2+h]
#pragma unroll
    for (int fn = 0; fn < 8; fn++)
#pragma unroll
        for (int h = 0; h < 2; h++)
            y2v[fn * 2 + h] = sy2b[wc * 64 + fn * 8 + 2 * lr + h];

    uint32_t rw[8];                 // [fm*2+hm][w2]
#pragma unroll
    for (int fm = 0; fm < 2; fm++)
#pragma unroll
        for (int hm = 0; hm < 2; hm++) {
            int grow = bi * BM + wr * 32 + fm * 16 + lq + hm * 8;
#pragma unroll
            for (int k = 0; k < 2; k++)
                rw[(fm * 2 + hm) * 2 + k] =
                    g_maskbits[(size_t)grow * (TWO_N / 32) + bj * 4 + wc * 2 + k];
        }

    uint32_t cw[16];                // [fn*2+h]
#pragma unroll
    for (int fn = 0; fn < 8; fn++)
#pragma unroll
        for (int h = 0; h < 2; h++) {
            int gcol = bj * BM + wc * 64 + fn * 8 + 2 * lr + h;
            cw[fn * 2 + h] = g_maskbits[(size_t)gcol * (TWO_N / 32) + bi * 4 + wr];
        }

    float rowp[4] = {0.f, 0.f, 0.f, 0.f};
    float colp[16];
#pragma unroll
    for (int i = 0; i < 16; i++) colp[i] = 0.f;

#pragma unroll
    for (int fm = 0; fm < 2; fm++)
#pragma unroll
        for (int fn = 0; fn < 8; fn++)
#pragma unroll
            for (int r = 0; r < 4; r++) {
                int hm = r >> 1, h = r & 1;
                int mloc = wr * 32 + fm * 16 + lq + hm * 8;
                int nloc = wc * 64 + fn * 8 + 2 * lr + h;
                float sq = x2v[fm * 2 + hm] + y2v[fn * 2 + h] - 2.f * acc[fm][fn][r];
                float dd = sqrtf(fmaxf(sq, 0.f) + 1e-12f);
                if (diag && mloc == nloc) dd = 1e-6f;   // exact self-distance
                if (ap_tile && mloc == nloc) g_ap[bj * BM + mloc] = dd;
                float ev = __expf(MARGIN - dd);
                int nn = fn * 8 + 2 * lr + h;           // 0..63 within wc half
                if ((rw[(fm * 2 + hm) * 2 + (nn >> 5)] >> (nn & 31)) & 1u)
                    rowp[fm * 2 + hm] += ev;
                if ((cw[fn * 2 + h] >> (fm * 16 + lq + hm * 8)) & 1u)
                    colp[fn * 2 + h] += ev;
            }

    // row partials: reduce over the 4-lane quad (lanes sharing lq)
#pragma unroll
    for (int i = 0; i < 4; i++) {
        rowp[i] += __shfl_xor_sync(0xffffffffu, rowp[i], 1);
        rowp[i] += __shfl_xor_sync(0xffffffffu, rowp[i], 2);
    }
    if (lr == 0) {
#pragma unroll
        for (int fm = 0; fm < 2; fm++)
#pragma unroll
            for (int hm = 0; hm < 2; hm++)
                rowred[wr * 32 + fm * 16 + lq + hm * 8][wc] = rowp[fm * 2 + hm];
    }

    // col partials: reduce over lq (xor 4, 8, 16)
#pragma unroll
    for (int i = 0; i < 16; i++) {
        colp[i] += __shfl_xor_sync(0xffffffffu, colp[i], 4);
        colp[i] += __shfl_xor_sync(0xffffffffu, colp[i], 8);
        colp[i] += __shfl_xor_sync(0xffffffffu, colp[i], 16);
    }
    if (lane < 4) {
#pragma unroll
        for (int fn = 0; fn < 8; fn++)
#pragma unroll
            for (int h = 0; h < 2; h++)
                colred[wc * 64 + fn * 8 + 2 * lane + h][wr] = colp[fn * 2 + h];
    }
    __syncthreads();

    if (tid < BM) {
        g_partial[(size_t)bj * TWO_N + bi * BM + tid] = rowred[tid][0] + rowred[tid][1];
        if (!diag)
            g_partial[(size_t)bi * TWO_N + bj * BM + tid] =
                colred[tid][0] + colred[tid][1] + colred[tid][2] + colred[tid][3];
    }
}

// ------------------------- reductions --------------------------------------
__global__ void rowsum_kernel() {
    int r = blockIdx.x * blockDim.x + threadIdx.x;
    if (r >= TWO_N) return;
    float s = 0.f;
#pragma unroll
    for (int c = 0; c < NBJ; c++) s += g_partial[(size_t)c * TWO_N + r];
    g_rowsum[r] = s;
}

__global__ void final_kernel(float* __restrict__ out) {
    __shared__ float ssum[256];
    __shared__ int   scnt[256];
    int tid = threadIdx.x;
    float s = 0.f;
    int   c = 0;
    for (int i = tid; i < NHALF; i += 256) {
        float rs = g_rowsum[i] + g_rowsum[i + NHALF];
        float j  = logf(rs) + g_ap[i];
        if (!isnan(j)) {
            c++;
            float tt = fmaxf(j, 0.f);
            s = fmaf(tt, tt, s);
        }
    }
    ssum[tid] = s;
    scnt[tid] = c;
    __syncthreads();
    for (int o = 128; o > 0; o >>= 1) {
        if (tid < o) { ssum[tid] += ssum[tid + o]; scnt[tid] += scnt[tid + o]; }
        __syncthreads();
    }
    if (tid == 0) {
        float cnt = fmaxf((float)scnt[0], 1.f);
        out[0] = ssum[0] / cnt * 0.5f;
    }
}

// ---------------------------------------------------------------------------
extern "C" void kernel_launch(void* const* d_in, const int* in_sizes, int n_in,
                              void* d_out, int out_size) {
    const float* E    = (const float*)d_in[0];
    const void*  mask = d_in[1];
    float*       out  = (float*)d_out;

    detect_mask_kernel<<<1, 256>>>((const unsigned int*)mask);
    prep_kernel<<<(TWO_N * 32) / 256, 256>>>(E);

    tile_kernel<<<NTILE, 256>>>(mask);

    rowsum_kernel<<<TWO_N / 256, 256>>>();
    final_kernel<<<1, 256>>>(out);
}

// round 7
// speedup vs baseline: 5.4136x; 1.1748x over previous
#include <cuda_runtime.h>
#include <cuda_fp16.h>
#include <math.h>
#include <stdint.h>

#define TWO_N 8192
#define DDIM  256
#define NHALF 4096
#define BM    128
#define NBJ   64
#define NTILE (NBJ * (NBJ + 1) / 2)   /* 2080 lower-triangle pairs */
#define MARGIN 0.5f
#define NCHUNK 8                       /* 8 chunks of K=32 */
#define NSTAGE 4
#define ROWB   80                      /* smem row stride bytes (32 halfs + 8 pad) */
#define STAGEB (BM * ROWB)             /* 10240 B per (A or B) stage */

/* dynamic smem layout (bytes) */
#define OFF_STAGES  0                              /* 4 stages x (A,B) */
#define OFF_MROW    (NSTAGE * 2 * STAGEB)          /* 81920: row-rect mask 2KB */
#define OFF_MCOL    (OFF_MROW + 2048)              /* col-rect mask 2KB */
#define OFF_SY2A    (OFF_MCOL + 2048)
#define OFF_SY2B    (OFF_SY2A + 512)
#define OFF_ROWRED  (OFF_SY2B + 512)               /* 128*2 floats */
#define OFF_COLRED  (OFF_ROWRED + 1024)            /* 128*4 floats */
#define SMEM_TOTAL  (OFF_COLRED + 2048)            /* 90112 B */

// ------------------------- device scratch (no allocs allowed) --------------
__device__ float    g_sqnorm[TWO_N];
__device__ float    g_partial[NBJ * TWO_N];
__device__ float    g_ap[NHALF];
__device__ float    g_rowsum[TWO_N];
__device__ int      g_mask_mode;   // 0=int32 1=uint8 2=float32 3=bf16
__device__ __half   g_eh[TWO_N * DDIM];                 // 4 MB fp16 embeddings

// ------------------------- helpers -----------------------------------------
__device__ __forceinline__ uint32_t smem_u32(const void* p) {
    uint32_t a;
    asm("{ .reg .u64 t; cvta.to.shared.u64 t, %1; cvt.u32.u64 %0, t; }"
        : "=r"(a) : "l"(p));
    return a;
}
__device__ __forceinline__ void cpa16(uint32_t dst, const void* src) {
    asm volatile("cp.async.cg.shared.global [%0], [%1], 16;" :: "r"(dst), "l"(src));
}
__device__ __forceinline__ void cpa_commit() {
    asm volatile("cp.async.commit_group;" ::: "memory");
}
template <int N>
__device__ __forceinline__ void cpa_wait() {
    asm volatile("cp.async.wait_group %0;" :: "n"(N) : "memory");
}
__device__ __forceinline__ void ldmx4(uint32_t* r, uint32_t addr) {
    asm volatile("ldmatrix.sync.aligned.m8n8.x4.shared.b16 {%0,%1,%2,%3}, [%4];"
                 : "=r"(r[0]), "=r"(r[1]), "=r"(r[2]), "=r"(r[3]) : "r"(addr));
}
__device__ __forceinline__ void mma16816(float* c, const uint32_t* a, const uint32_t* b) {
    asm volatile(
        "mma.sync.aligned.m16n8k16.row.col.f32.f16.f16.f32 "
        "{%0,%1,%2,%3}, {%4,%5,%6,%7}, {%8,%9}, {%0,%1,%2,%3};"
        : "+f"(c[0]), "+f"(c[1]), "+f"(c[2]), "+f"(c[3])
        : "r"(a[0]), "r"(a[1]), "r"(a[2]), "r"(a[3]), "r"(b[0]), "r"(b[1]));
}

// ------------------------- small kernels -----------------------------------
__global__ void detect_mask_kernel(const unsigned int* __restrict__ m) {
    __shared__ int has_gt1, has_f32one, has_bf16pat;
    if (threadIdx.x == 0) { has_gt1 = 0; has_f32one = 0; has_bf16pat = 0; }
    __syncthreads();
    for (int i = threadIdx.x; i < 1024; i += blockDim.x) {
        unsigned int w = m[i];
        if (w == 0x3F803F80u || w == 0x00003F80u) atomicOr(&has_bf16pat, 1);
        else if (w == 0x3F800000u)                atomicOr(&has_f32one, 1);
        else if (w > 1u)                          atomicOr(&has_gt1, 1);
    }
    __syncthreads();
    if (threadIdx.x == 0) {
        int mode;
        if (has_bf16pat)      mode = 3;
        else if (has_f32one)  mode = 2;
        else if (has_gt1)     mode = 1;
        else                  mode = 0;
        g_mask_mode = mode;
    }
}

// fused: squared norm + fp16 conversion, one warp per row
__global__ void prep_kernel(const float* __restrict__ E) {
    int warp = (blockIdx.x * blockDim.x + threadIdx.x) >> 5;
    int lane = threadIdx.x & 31;
    if (warp >= TWO_N) return;
    const float* row = E + (size_t)warp * DDIM;
    float4 v0 = ((const float4*)row)[lane * 2];
    float4 v1 = ((const float4*)row)[lane * 2 + 1];
    float s = v0.x * v0.x;
    s = fmaf(v0.y, v0.y, s); s = fmaf(v0.z, v0.z, s); s = fmaf(v0.w, v0.w, s);
    s = fmaf(v1.x, v1.x, s); s = fmaf(v1.y, v1.y, s);
    s = fmaf(v1.z, v1.z, s); s = fmaf(v1.w, v1.w, s);
    __half2 h[4];
    h[0] = __floats2half2_rn(v0.x, v0.y);
    h[1] = __floats2half2_rn(v0.z, v0.w);
    h[2] = __floats2half2_rn(v1.x, v1.y);
    h[3] = __floats2half2_rn(v1.z, v1.w);
    *(uint4*)(g_eh + (size_t)warp * DDIM + lane * 8) = *(uint4*)h;
#pragma unroll
    for (int o = 16; o > 0; o >>= 1) s += __shfl_xor_sync(0xffffffffu, s, o);
    if (lane == 0) g_sqnorm[warp] = s;
}

// ------------------------- per-tile mask packing into smem ------------------
__device__ __forceinline__ void pack_rect(const void* __restrict__ mraw, int mode,
                                          int rowbase, int colbase,
                                          uint32_t* __restrict__ dst, int tid) {
#pragma unroll
    for (int w = tid; w < 512; w += 256) {
        int rr = w >> 2, wq = w & 3;
        size_t ebase = (size_t)(rowbase + rr) * TWO_N + colbase + wq * 32;
        uint32_t bits = 0u;
        if (mode == 0 || mode == 2) {              // int32 / float32 (4 B/elem)
            const uint4* p = (const uint4*)mraw + (ebase >> 2);
            uint32_t vm = (mode == 2) ? 0x7fffffffu : 0xffffffffu;
#pragma unroll
            for (int q = 0; q < 8; q++) {
                uint4 v = p[q];
                bits |= ((uint32_t)((v.x & vm) != 0u)) << (q * 4 + 0);
                bits |= ((uint32_t)((v.y & vm) != 0u)) << (q * 4 + 1);
                bits |= ((uint32_t)((v.z & vm) != 0u)) << (q * 4 + 2);
                bits |= ((uint32_t)((v.w & vm) != 0u)) << (q * 4 + 3);
            }
        } else if (mode == 1) {                    // uint8
            const uint4* p = (const uint4*)mraw + (ebase >> 4);
#pragma unroll
            for (int q = 0; q < 2; q++) {
                uint4 v = p[q];
                uint32_t ws[4] = {v.x, v.y, v.z, v.w};
#pragma unroll
                for (int k = 0; k < 4; k++)
#pragma unroll
                    for (int b = 0; b < 4; b++)
                        bits |= ((uint32_t)(((ws[k] >> (8 * b)) & 0xffu) != 0u))
                                << (q * 16 + k * 4 + b);
            }
        } else {                                   // bf16
            const uint4* p = (const uint4*)mraw + (ebase >> 3);
#pragma unroll
            for (int q = 0; q < 4; q++) {
                uint4 v = p[q];
                uint32_t ws[4] = {v.x, v.y, v.z, v.w};
#pragma unroll
                for (int k = 0; k < 4; k++) {
                    bits |= ((uint32_t)((ws[k] & 0x7fffu) != 0u))         << (q * 8 + k * 2 + 0);
                    bits |= ((uint32_t)(((ws[k] >> 16) & 0x7fffu) != 0u)) << (q * 8 + k * 2 + 1);
                }
            }
        }
        dst[w] = bits;
    }
}

// ------------------------- fused HMMA tile kernel ---------------------------
extern __shared__ __align__(16) unsigned char dynsm[];

__global__ void __launch_bounds__(256, 2)
tile_kernel(const void* __restrict__ mraw) {
    // linear tile index -> (bi, bj), bi >= bj
    int t = blockIdx.x;
    int bi = (int)((sqrt(8.0 * t + 1.0) - 1.0) * 0.5);
    while ((bi + 1) * (bi + 2) / 2 <= t) bi++;
    while (bi * (bi + 1) / 2 > t) bi--;
    int bj = t - bi * (bi + 1) / 2;
    const bool diag    = (bi == bj);
    const bool ap_tile = (bi == bj + 32);

    const int tid  = threadIdx.x;
    const int wid  = tid >> 5;
    const int lane = tid & 31;
    const int wr   = wid & 3;     // warp row: 4 x 32 rows
    const int wc   = wid >> 2;    // warp col: 2 x 64 cols

    const uint32_t smb = smem_u32(dynsm);
    float*    sy2a  = (float*)(dynsm + OFF_SY2A);
    float*    sy2b  = (float*)(dynsm + OFF_SY2B);
    uint32_t* mrow  = (uint32_t*)(dynsm + OFF_MROW);
    uint32_t* mcol  = (uint32_t*)(dynsm + OFF_MCOL);
    float (*rowred)[2] = (float (*)[2])(dynsm + OFF_ROWRED);
    float (*colred)[4] = (float (*)[4])(dynsm + OFF_COLRED);

    if (tid < BM) sy2a[tid] = g_sqnorm[bi * BM + tid];
    else          sy2b[tid - BM] = g_sqnorm[bj * BM + (tid - BM)];

    // global-load mapping: 512 x 16B per 128x32 tile, 2 per thread
    const int lrow0 = tid >> 2;          // rows 0..63
    const int lrow1 = lrow0 + 64;        // rows 64..127
    const int q0    = tid & 3;           // 16B quad within 64B row-chunk

    const __half* pa_base = g_eh + (size_t)bi * BM * DDIM;
    const __half* pb_base = g_eh + (size_t)bj * BM * DDIM;
    const uint32_t sA0 = (uint32_t)(lrow0 * ROWB + q0 * 16);
    const uint32_t sA1 = (uint32_t)(lrow1 * ROWB + q0 * 16);

    // prologue: issue cp.async for chunks 0..2
#pragma unroll
    for (int s = 0; s < NSTAGE - 1; s++) {
        int k0 = s * 32;
        uint32_t ab = smb + s * 2 * STAGEB;
        uint32_t bb = ab + STAGEB;
        cpa16(ab + sA0, pa_base + (size_t)lrow0 * DDIM + k0 + q0 * 8);
        cpa16(ab + sA1, pa_base + (size_t)lrow1 * DDIM + k0 + q0 * 8);
        cpa16(bb + sA0, pb_base + (size_t)lrow0 * DDIM + k0 + q0 * 8);
        cpa16(bb + sA1, pb_base + (size_t)lrow1 * DDIM + k0 + q0 * 8);
        cpa_commit();
    }

    // per-tile mask packing into smem (LDG latency overlaps cp.async drain)
    {
        int mode = g_mask_mode;
        pack_rect(mraw, mode, bi * BM, bj * BM, mrow, tid);
        if (!diag) pack_rect(mraw, mode, bj * BM, bi * BM, mcol, tid);
    }

    // ldmatrix per-lane byte offsets
    const uint32_t aoff = (uint32_t)((wr * 32 + (lane & 15)) * ROWB + (lane >> 4) * 16);
    const uint32_t boff = (uint32_t)((wc * 64 + ((lane >> 4) & 1) * 8 + (lane & 7)) * ROWB
                                     + ((lane >> 3) & 1) * 16);

    float acc[2][8][4];
#pragma unroll
    for (int i = 0; i < 2; i++)
#pragma unroll
        for (int j = 0; j < 8; j++)
#pragma unroll
            for (int r = 0; r < 4; r++) acc[i][j][r] = 0.f;

    for (int c = 0; c < NCHUNK; c++) {
        cpa_wait<NSTAGE - 2>();   // stage c arrived
        __syncthreads();          // + all threads done computing stage c-1

        if (c + NSTAGE - 1 < NCHUNK) {
            int k0 = (c + NSTAGE - 1) * 32;
            int s  = (c + NSTAGE - 1) & (NSTAGE - 1);
            uint32_t ab = smb + s * 2 * STAGEB;
            uint32_t bb = ab + STAGEB;
            cpa16(ab + sA0, pa_base + (size_t)lrow0 * DDIM + k0 + q0 * 8);
            cpa16(ab + sA1, pa_base + (size_t)lrow1 * DDIM + k0 + q0 * 8);
            cpa16(bb + sA0, pb_base + (size_t)lrow0 * DDIM + k0 + q0 * 8);
            cpa16(bb + sA1, pb_base + (size_t)lrow1 * DDIM + k0 + q0 * 8);
        }
        cpa_commit();

        const uint32_t aB = smb + (c & (NSTAGE - 1)) * 2 * STAGEB + aoff;
        const uint32_t bB = aB - aoff + STAGEB + boff;
#pragma unroll
        for (int ks = 0; ks < 2; ks++) {
            uint32_t afr[2][4];
            ldmx4(afr[0], aB + ks * 32);
            ldmx4(afr[1], aB + 16 * ROWB + ks * 32);
            uint32_t bfr[8][2];
#pragma unroll
            for (int fp = 0; fp < 4; fp++) {
                uint32_t r4[4];
                ldmx4(r4, bB + fp * 16 * ROWB + ks * 32);
                bfr[fp * 2 + 0][0] = r4[0]; bfr[fp * 2 + 0][1] = r4[1];
                bfr[fp * 2 + 1][0] = r4[2]; bfr[fp * 2 + 1][1] = r4[3];
            }
#pragma unroll
            for (int fm = 0; fm < 2; fm++)
#pragma unroll
                for (int fn = 0; fn < 8; fn++)
                    mma16816(acc[fm][fn], afr[fm], bfr[fn]);
        }
    }
    __syncthreads();   // mask pack + all MMA consumption done

    // ------------------------------ epilogue -------------------------------
    const int lq = lane >> 2;       // 0..7
    const int lr = lane & 3;        // 0..3
    const uint32_t* colm = diag ? mrow : mcol;

    float x2v[4];
#pragma unroll
    for (int fm = 0; fm < 2; fm++)
#pragma unroll
        for (int hm = 0; hm < 2; hm++)
            x2v[fm * 2 + hm] = sy2a[wr * 32 + fm * 16 + lq + hm * 8];

    float y2v[16];
#pragma unroll
    for (int fn = 0; fn < 8; fn++)
#pragma unroll
        for (int h = 0; h < 2; h++)
            y2v[fn * 2 + h] = sy2b[wc * 64 + fn * 8 + 2 * lr + h];

    uint32_t rw[8];
#pragma unroll
    for (int fm = 0; fm < 2; fm++)
#pragma unroll
        for (int hm = 0; hm < 2; hm++) {
            int mloc = wr * 32 + fm * 16 + lq + hm * 8;
#pragma unroll
            for (int k = 0; k < 2; k++)
                rw[(fm * 2 + hm) * 2 + k] = mrow[mloc * 4 + wc * 2 + k];
        }

    uint32_t cw[16];
#pragma unroll
    for (int fn = 0; fn < 8; fn++)
#pragma unroll
        for (int h = 0; h < 2; h++) {
            int nloc = wc * 64 + fn * 8 + 2 * lr + h;
            cw[fn * 2 + h] = colm[nloc * 4 + wr];
        }

    float rowp[4] = {0.f, 0.f, 0.f, 0.f};
    float colp[16];
#pragma unroll
    for (int i = 0; i < 16; i++) colp[i] = 0.f;

#pragma unroll
    for (int fm = 0; fm < 2; fm++)
#pragma unroll
        for (int fn = 0; fn < 8; fn++)
#pragma unroll
            for (int r = 0; r < 4; r++) {
                int hm = r >> 1, h = r & 1;
                int mloc = wr * 32 + fm * 16 + lq + hm * 8;
                int nloc = wc * 64 + fn * 8 + 2 * lr + h;
                float sq = x2v[fm * 2 + hm] + y2v[fn * 2 + h] - 2.f * acc[fm][fn][r];
                float dd = sqrtf(fmaxf(sq, 0.f) + 1e-12f);
                if (diag && mloc == nloc) dd = 1e-6f;   // exact self-distance
                if (ap_tile && mloc == nloc) g_ap[bj * BM + mloc] = dd;
                float ev = __expf(MARGIN - dd);
                int nn = fn * 8 + 2 * lr + h;           // 0..63 within wc half
                if ((rw[(fm * 2 + hm) * 2 + (nn >> 5)] >> (nn & 31)) & 1u)
                    rowp[fm * 2 + hm] += ev;
                if ((cw[fn * 2 + h] >> (fm * 16 + lq + hm * 8)) & 1u)
                    colp[fn * 2 + h] += ev;
            }

    // row partials: reduce over the 4-lane quad
#pragma unroll
    for (int i = 0; i < 4; i++) {
        rowp[i] += __shfl_xor_sync(0xffffffffu, rowp[i], 1);
        rowp[i] += __shfl_xor_sync(0xffffffffu, rowp[i], 2);
    }
    if (lr == 0) {
#pragma unroll
        for (int fm = 0; fm < 2; fm++)
#pragma unroll
            for (int hm = 0; hm < 2; hm++)
                rowred[wr * 32 + fm * 16 + lq + hm * 8][wc] = rowp[fm * 2 + hm];
    }

    // col partials: reduce over lq (xor 4, 8, 16)
#pragma unroll
    for (int i = 0; i < 16; i++) {
        colp[i] += __shfl_xor_sync(0xffffffffu, colp[i], 4);
        colp[i] += __shfl_xor_sync(0xffffffffu, colp[i], 8);
        colp[i] += __shfl_xor_sync(0xffffffffu, colp[i], 16);
    }
    if (lane < 4) {
#pragma unroll
        for (int fn = 0; fn < 8; fn++)
#pragma unroll
            for (int h = 0; h < 2; h++)
                colred[wc * 64 + fn * 8 + 2 * lane + h][wr] = colp[fn * 2 + h];
    }
    __syncthreads();

    if (tid < BM) {
        g_partial[(size_t)bj * TWO_N + bi * BM + tid] = rowred[tid][0] + rowred[tid][1];
        if (!diag)
            g_partial[(size_t)bi * TWO_N + bj * BM + tid] =
                colred[tid][0] + colred[tid][1] + colred[tid][2] + colred[tid][3];
    }
}

// ------------------------- reductions --------------------------------------
__global__ void rowsum_kernel() {
    int r = blockIdx.x * blockDim.x + threadIdx.x;
    if (r >= TWO_N) return;
    float s = 0.f;
#pragma unroll
    for (int c = 0; c < NBJ; c++) s += g_partial[(size_t)c * TWO_N + r];
    g_rowsum[r] = s;
}

__global__ void final_kernel(float* __restrict__ out) {
    __shared__ float ssum[256];
    __shared__ int   scnt[256];
    int tid = threadIdx.x;
    float s = 0.f;
    int   c = 0;
    for (int i = tid; i < NHALF; i += 256) {
        float rs = g_rowsum[i] + g_rowsum[i + NHALF];
        float j  = logf(rs) + g_ap[i];
        if (!isnan(j)) {
            c++;
            float tt = fmaxf(j, 0.f);
            s = fmaf(tt, tt, s);
        }
    }
    ssum[tid] = s;
    scnt[tid] = c;
    __syncthreads();
    for (int o = 128; o > 0; o >>= 1) {
        if (tid < o) { ssum[tid] += ssum[tid + o]; scnt[tid] += scnt[tid + o]; }
        __syncthreads();
    }
    if (tid == 0) {
        float cnt = fmaxf((float)scnt[0], 1.f);
        out[0] = ssum[0] / cnt * 0.5f;
    }
}

// ---------------------------------------------------------------------------
extern "C" void kernel_launch(void* const* d_in, const int* in_sizes, int n_in,
                              void* d_out, int out_size) {
    const float* E    = (const float*)d_in[0];
    const void*  mask = d_in[1];
    float*       out  = (float*)d_out;

    detect_mask_kernel<<<1, 256>>>((const unsigned int*)mask);
    prep_kernel<<<(TWO_N * 32) / 256, 256>>>(E);

    cudaFuncSetAttribute(tile_kernel, cudaFuncAttributeMaxDynamicSharedMemorySize,
                         SMEM_TOTAL);
    tile_kernel<<<NTILE, 256, SMEM_TOTAL>>>(mask);

    rowsum_kernel<<<TWO_N / 256, 256>>>();
    final_kernel<<<1, 256>>>(out);
}